// round 12
// baseline (speedup 1.0000x reference)
#include <cuda_runtime.h>
#include <stdint.h>

#define D 16
#define MAX_NODES 50000

__device__ float g_key_n[MAX_NODES * D];
__device__ float g_sum[MAX_NODES];

__device__ __forceinline__ float dot4(float4 a, float4 b) {
    return a.x * b.x + a.y * b.y + a.z * b.z + a.w * b.w;
}

__device__ __forceinline__ void cp_async16(void* smem_dst, const void* gmem_src) {
    unsigned sa = (unsigned)__cvta_generic_to_shared(smem_dst);
    asm volatile("cp.async.ca.shared.global [%0], [%1], 16;\n"
                 :: "r"(sa), "l"(gmem_src) : "memory");
}

// Kernel 1: key_n[n,i] = feat[n,i] * rowsum(W_n[n,i,:]) + b_n[n,i]
// cp.async staging: each warp owns 2 tiles of 32 rows. 8 LDGSTS per thread
// (global->smem direct, no register staging, deep MLP) + front-batched
// feat/b_n LDGs, single wait + syncwarp, then 2 conflict-free LDS.128
// reduce phases (row stride 20 floats) and coalesced stores.
// total_rows = 800000 = 25000 tiles exactly -> no ragged tail.
__global__ void __launch_bounds__(256) node_prep_kernel(
        const float* __restrict__ feat,
        const float* __restrict__ w_n,
        const float* __restrict__ b_n,
        int n_nodes) {
    __shared__ float sw[8][2][32 * 20];     // per-warp, 2 slabs of 2560B

    int w = threadIdx.x >> 5;
    int l = threadIdx.x & 31;
    int gw = blockIdx.x * 8 + w;
    int total_rows = n_nodes * D;
    int ntiles = (total_rows + 31) >> 5;

    int t0 = gw * 2;
    int t1 = gw * 2 + 1;
    bool live0 = t0 < ntiles;
    bool live1 = t1 < ntiles;

    const float4* w4p = reinterpret_cast<const float4*>(w_n);

    // Issue all async copies front-batched (zero register cost).
    if (live0) {
        #pragma unroll
        for (int r = 0; r < 4; r++) {
            int g = r * 32 + l;
            cp_async16(&sw[w][0][(g >> 2) * 20 + (g & 3) * 4],
                       w4p + (size_t)t0 * 128 + r * 32 + l);
        }
    }
    if (live1) {
        #pragma unroll
        for (int r = 0; r < 4; r++) {
            int g = r * 32 + l;
            cp_async16(&sw[w][1][(g >> 2) * 20 + (g & 3) * 4],
                       w4p + (size_t)t1 * 128 + r * 32 + l);
        }
    }
    asm volatile("cp.async.commit_group;\n" ::: "memory");

    // Front-batch the independent per-row loads while copies are in flight.
    int i0 = t0 * 32 + l;
    int i1 = t1 * 32 + l;
    float f0 = 0.f, bb0 = 0.f, f1 = 0.f, bb1 = 0.f;
    if (live0 && i0 < total_rows) { f0 = __ldg(&feat[i0]); bb0 = __ldg(&b_n[i0]); }
    if (live1 && i1 < total_rows) { f1 = __ldg(&feat[i1]); bb1 = __ldg(&b_n[i1]); }

    asm volatile("cp.async.wait_group 0;\n" ::: "memory");
    __syncwarp();

    // Reduce own row of each slab (conflict-free: 20*l mod 32 distinct
    // within each 8-lane phase).
    if (live0 && i0 < total_rows) {
        const float4* r4 = reinterpret_cast<const float4*>(&sw[w][0][l * 20]);
        float4 a = r4[0], b = r4[1], c = r4[2], d = r4[3];
        float rs = ((a.x + a.y) + (a.z + a.w)) + ((b.x + b.y) + (b.z + b.w))
                 + ((c.x + c.y) + (c.z + c.w)) + ((d.x + d.y) + (d.z + d.w));
        g_key_n[i0] = f0 * rs + bb0;
        if (i0 < n_nodes) g_sum[i0] = 0.0f;
    }
    if (live1 && i1 < total_rows) {
        const float4* r4 = reinterpret_cast<const float4*>(&sw[w][1][l * 20]);
        float4 a = r4[0], b = r4[1], c = r4[2], d = r4[3];
        float rs = ((a.x + a.y) + (a.z + a.w)) + ((b.x + b.y) + (b.z + b.w))
                 + ((c.x + c.y) + (c.z + c.w)) + ((d.x + d.y) + (d.z + d.w));
        g_key_n[i1] = f1 * rs + bb1;
        if (i1 < n_nodes) g_sum[i1] = 0.0f;
    }
}

// Kernel 2: the 512MB streamer, W-coalesced (unchanged — ~85us, at the
// measured ceiling).
// 16 lanes per edge. Lane d loads float4 w4[d + 16k], k=0..3 (consecutive
// lanes -> consecutive 16B). Float4 j=d+16k is chunk c=d&3 of row
// r=4k+(d>>2). Bilinear: each lane accumulates q[r]*dot(w4, f_chunk[c]);
// summation order irrelevant -> single 16-lane xor reduce.
// exp() without max-shift (|logit| small; softmax ratio identical);
// per-dst denominator via atomicAdd.
__global__ void __launch_bounds__(256) edge_logits_kernel(
                                   const float* __restrict__ feat,
                                   const float* __restrict__ query,
                                   const float* __restrict__ w_e,
                                   const float* __restrict__ b_e,
                                   const int* __restrict__ src,
                                   const int* __restrict__ dst,
                                   float* __restrict__ out,
                                   int n_edges) {
    int t = blockIdx.x * blockDim.x + threadIdx.x;
    int e = t >> 4;
    int d = t & 15;
    if (e >= n_edges) return;

    int sN = __ldg(&src[e]);
    int dN = __ldg(&dst[e]);

    int a = d >> 2;   // row group
    int c = d & 3;    // chunk

    float4 fc = __ldg(reinterpret_cast<const float4*>(feat + (size_t)sN * D) + c);

    const float4* w4 = reinterpret_cast<const float4*>(w_e + (size_t)e * (D * D));
    float4 wa = w4[d];
    float4 wb = w4[d + 16];
    float4 wc = w4[d + 32];
    float4 wd = w4[d + 48];

    const float* q = query + (size_t)dN * D;
    float p = dot4(wa, fc) * __ldg(&q[a])
            + dot4(wb, fc) * __ldg(&q[a + 4])
            + dot4(wc, fc) * __ldg(&q[a + 8])
            + dot4(wd, fc) * __ldg(&q[a + 12]);

    float f_d = __ldg(&feat[(size_t)sN * D + d]);
    float lin = __ldg(&b_e[(size_t)e * D + d]) + f_d + __ldg(&g_key_n[(size_t)sN * D + d]);
    p += lin * __ldg(&q[d]);

    #pragma unroll
    for (int off = 8; off > 0; off >>= 1)
        p += __shfl_xor_sync(0xffffffffu, p, off, 16);

    if (d == 0) {
        float ex = __expf(p);
        out[e] = ex;
        atomicAdd(&g_sum[dN], ex);
    }
}

// Kernel 3: normalize, 8 edges per thread, front-batched, reciprocal mult.
__global__ void edge_norm_kernel(const int* __restrict__ dst,
                                 float* __restrict__ out,
                                 int n_edges) {
    int i = blockIdx.x * blockDim.x + threadIdx.x;
    int e = i * 8;
    if (e + 7 < n_edges) {
        int4   dn0 = *reinterpret_cast<const int4*>(dst + e);
        int4   dn1 = *reinterpret_cast<const int4*>(dst + e + 4);
        float4 o0  = *reinterpret_cast<float4*>(out + e);
        float4 o1  = *reinterpret_cast<float4*>(out + e + 4);
        float s0 = g_sum[dn0.x], s1 = g_sum[dn0.y], s2 = g_sum[dn0.z], s3 = g_sum[dn0.w];
        float s4 = g_sum[dn1.x], s5 = g_sum[dn1.y], s6 = g_sum[dn1.z], s7 = g_sum[dn1.w];
        o0.x *= __frcp_rn(s0); o0.y *= __frcp_rn(s1);
        o0.z *= __frcp_rn(s2); o0.w *= __frcp_rn(s3);
        o1.x *= __frcp_rn(s4); o1.y *= __frcp_rn(s5);
        o1.z *= __frcp_rn(s6); o1.w *= __frcp_rn(s7);
        *reinterpret_cast<float4*>(out + e)     = o0;
        *reinterpret_cast<float4*>(out + e + 4) = o1;
    } else {
        for (; e < n_edges; e++)
            out[e] /= g_sum[__ldg(&dst[e])];
    }
}

extern "C" void kernel_launch(void* const* d_in, const int* in_sizes, int n_in,
                              void* d_out, int out_size) {
    const float* feat  = (const float*)d_in[0];   // [N,16]
    const float* w_n   = (const float*)d_in[1];   // [N,16,16]
    const float* b_n   = (const float*)d_in[2];   // [N,16]
    const float* query = (const float*)d_in[3];   // [N,16]
    const float* w_e   = (const float*)d_in[4];   // [E,16,16]
    const float* b_e   = (const float*)d_in[5];   // [E,16]
    const int*   src   = (const int*)d_in[6];     // [E]
    const int*   dst   = (const int*)d_in[7];     // [E]
    float* out = (float*)d_out;                   // [E,1]

    int n_nodes = in_sizes[0] / D;
    int n_edges = in_sizes[7];

    {
        int total_rows = n_nodes * D;
        int ntiles = (total_rows + 31) / 32;        // 25000
        int warps = (ntiles + 1) / 2;               // 2 tiles per warp
        int blocks = (warps + 7) / 8;               // 8 warps per CTA
        node_prep_kernel<<<blocks, 256>>>(feat, w_n, b_n, n_nodes);
    }
    {
        long long total = (long long)n_edges * D;
        int bs = 256;
        int grid = (int)((total + bs - 1) / bs);
        edge_logits_kernel<<<grid, bs>>>(feat, query, w_e, b_e, src, dst, out, n_edges);
    }
    {
        int bs = 256;
        int octs = (n_edges + 7) / 8;
        int grid = (octs + bs - 1) / bs;
        edge_norm_kernel<<<grid, bs>>>(dst, out, n_edges);
    }
}

// round 13
// speedup vs baseline: 1.1148x; 1.1148x over previous
#include <cuda_runtime.h>
#include <stdint.h>

#define D 16
#define MAX_NODES 50000

__device__ float g_key_n[MAX_NODES * D];
__device__ float g_sum[MAX_NODES];

__device__ __forceinline__ float dot4(float4 a, float4 b) {
    return a.x * b.x + a.y * b.y + a.z * b.z + a.w * b.w;
}

// Kernel 1: key_n[n,i] = feat[n,i] * rowsum(W_n[n,i,:]) + b_n[n,i]
// R7 warp-local staging (best measured: 12.6us). Each warp owns 32 rows:
// 4 coalesced 512B LDG.128 rounds (streaming/evict-first: w_n is one-shot)
// -> private smem slab (row stride 20 floats, conflict-free LDS.128) ->
// __syncwarp -> lane l reduces row l. feat/b_n front-batched. No block
// barrier, no pipeline registers, smem 2.5KB/warp.
__global__ void __launch_bounds__(256) node_prep_kernel(
        const float* __restrict__ feat,
        const float* __restrict__ w_n,
        const float* __restrict__ b_n,
        int n_nodes) {
    __shared__ float sw[8][32 * 20];        // per-warp slab, 2560B each

    int tid = threadIdx.x;
    int w = tid >> 5;
    int l = tid & 31;
    int total_rows = n_nodes * D;           // 800000
    int total4 = total_rows * 4;
    int rowbase = blockIdx.x * 256;
    int i = rowbase + tid;                  // this thread's output row
    bool live = i < total_rows;

    float f_i = live ? __ldg(&feat[i]) : 0.f;
    float b_i = live ? __ldg(&b_n[i])  : 0.f;

    int base4 = (rowbase + w * 32) * 4;
    float4 v[4];
    #pragma unroll
    for (int r = 0; r < 4; r++) {
        int idx = base4 + r * 32 + l;
        v[r] = (idx < total4)
             ? __ldcs(reinterpret_cast<const float4*>(w_n) + idx)
             : make_float4(0.f, 0.f, 0.f, 0.f);
    }
    #pragma unroll
    for (int r = 0; r < 4; r++) {
        int g = r * 32 + l;                 // local float4 index 0..127
        *reinterpret_cast<float4*>(&sw[w][(g >> 2) * 20 + (g & 3) * 4]) = v[r];
    }
    __syncwarp();

    const float4* r4 = reinterpret_cast<const float4*>(&sw[w][l * 20]);
    float4 a = r4[0], b = r4[1], c = r4[2], d = r4[3];
    float rs = ((a.x + a.y) + (a.z + a.w)) + ((b.x + b.y) + (b.z + b.w))
             + ((c.x + c.y) + (c.z + c.w)) + ((d.x + d.y) + (d.z + d.w));

    if (live) {
        g_key_n[i] = f_i * rs + b_i;
        if (i < n_nodes) g_sum[i] = 0.0f;
    }
}

// Kernel 2: the 512MB streamer, W-coalesced. One-shot streams (w_e, b_e)
// use __ldcs (evict-first) so they don't displace the L2-resident gather
// set (feat/query/g_key_n/src/dst, ~12MB).
// 16 lanes per edge. Lane d loads float4 w4[d + 16k], k=0..3 (consecutive
// lanes -> consecutive 16B). Float4 j=d+16k is chunk c=d&3 of row
// r=4k+(d>>2). Bilinear: each lane accumulates q[r]*dot(w4, f_chunk[c]);
// summation order irrelevant -> single 16-lane xor reduce.
// exp() without max-shift (|logit| small; softmax ratio identical);
// per-dst denominator via atomicAdd.
__global__ void __launch_bounds__(256) edge_logits_kernel(
                                   const float* __restrict__ feat,
                                   const float* __restrict__ query,
                                   const float* __restrict__ w_e,
                                   const float* __restrict__ b_e,
                                   const int* __restrict__ src,
                                   const int* __restrict__ dst,
                                   float* __restrict__ out,
                                   int n_edges) {
    int t = blockIdx.x * blockDim.x + threadIdx.x;
    int e = t >> 4;
    int d = t & 15;
    if (e >= n_edges) return;

    int sN = __ldg(&src[e]);
    int dN = __ldg(&dst[e]);

    int a = d >> 2;   // row group
    int c = d & 3;    // chunk

    float4 fc = __ldg(reinterpret_cast<const float4*>(feat + (size_t)sN * D) + c);

    const float4* w4 = reinterpret_cast<const float4*>(w_e + (size_t)e * (D * D));
    float4 wa = __ldcs(w4 + d);
    float4 wb = __ldcs(w4 + d + 16);
    float4 wc = __ldcs(w4 + d + 32);
    float4 wd = __ldcs(w4 + d + 48);

    const float* q = query + (size_t)dN * D;
    float p = dot4(wa, fc) * __ldg(&q[a])
            + dot4(wb, fc) * __ldg(&q[a + 4])
            + dot4(wc, fc) * __ldg(&q[a + 8])
            + dot4(wd, fc) * __ldg(&q[a + 12]);

    float f_d = __ldg(&feat[(size_t)sN * D + d]);
    float lin = __ldcs(&b_e[(size_t)e * D + d]) + f_d + __ldg(&g_key_n[(size_t)sN * D + d]);
    p += lin * __ldg(&q[d]);

    #pragma unroll
    for (int off = 8; off > 0; off >>= 1)
        p += __shfl_xor_sync(0xffffffffu, p, off, 16);

    if (d == 0) {
        float ex = __expf(p);
        out[e] = ex;
        atomicAdd(&g_sum[dN], ex);
    }
}

// Kernel 3: normalize, 8 edges per thread, front-batched, reciprocal mult.
// out/dst are one-shot streams here too -> __ldcs.
__global__ void edge_norm_kernel(const int* __restrict__ dst,
                                 float* __restrict__ out,
                                 int n_edges) {
    int i = blockIdx.x * blockDim.x + threadIdx.x;
    int e = i * 8;
    if (e + 7 < n_edges) {
        int4   dn0 = __ldcs(reinterpret_cast<const int4*>(dst + e));
        int4   dn1 = __ldcs(reinterpret_cast<const int4*>(dst + e + 4));
        float4 o0  = __ldcs(reinterpret_cast<const float4*>(out + e));
        float4 o1  = __ldcs(reinterpret_cast<const float4*>(out + e + 4));
        float s0 = g_sum[dn0.x], s1 = g_sum[dn0.y], s2 = g_sum[dn0.z], s3 = g_sum[dn0.w];
        float s4 = g_sum[dn1.x], s5 = g_sum[dn1.y], s6 = g_sum[dn1.z], s7 = g_sum[dn1.w];
        o0.x *= __frcp_rn(s0); o0.y *= __frcp_rn(s1);
        o0.z *= __frcp_rn(s2); o0.w *= __frcp_rn(s3);
        o1.x *= __frcp_rn(s4); o1.y *= __frcp_rn(s5);
        o1.z *= __frcp_rn(s6); o1.w *= __frcp_rn(s7);
        *reinterpret_cast<float4*>(out + e)     = o0;
        *reinterpret_cast<float4*>(out + e + 4) = o1;
    } else {
        for (; e < n_edges; e++)
            out[e] /= g_sum[__ldg(&dst[e])];
    }
}

extern "C" void kernel_launch(void* const* d_in, const int* in_sizes, int n_in,
                              void* d_out, int out_size) {
    const float* feat  = (const float*)d_in[0];   // [N,16]
    const float* w_n   = (const float*)d_in[1];   // [N,16,16]
    const float* b_n   = (const float*)d_in[2];   // [N,16]
    const float* query = (const float*)d_in[3];   // [N,16]
    const float* w_e   = (const float*)d_in[4];   // [E,16,16]
    const float* b_e   = (const float*)d_in[5];   // [E,16]
    const int*   src   = (const int*)d_in[6];     // [E]
    const int*   dst   = (const int*)d_in[7];     // [E]
    float* out = (float*)d_out;                   // [E,1]

    int n_nodes = in_sizes[0] / D;
    int n_edges = in_sizes[7];

    {
        int total_rows = n_nodes * D;
        int blocks = (total_rows + 255) / 256;    // 256 rows per block
        node_prep_kernel<<<blocks, 256>>>(feat, w_n, b_n, n_nodes);
    }
    {
        long long total = (long long)n_edges * D;
        int bs = 256;
        int grid = (int)((total + bs - 1) / bs);
        edge_logits_kernel<<<grid, bs>>>(feat, query, w_e, b_e, src, dst, out, n_edges);
    }
    {
        int bs = 256;
        int octs = (n_edges + 7) / 8;
        int grid = (octs + bs - 1) / bs;
        edge_norm_kernel<<<grid, bs>>>(dst, out, n_edges);
    }
}